// round 8
// baseline (speedup 1.0000x reference)
#include <cuda_runtime.h>
#include <math.h>

#define T_LEN 1024
#define B_SZ  64
#define H_SZ  256
#define D_SZ  256
#define C4    1024          // 4*H, col = j*4 + k (gates of a neuron contiguous)
#define NR    64            // recurrent CTAs, 4 neurons (16 gate cols) each
#define HS_STRIDE 72        // padded word stride for hs[d][b]
#define FLAG_STR 8          // 32B padding between flags

// ---------------- scratch (static device allocations only) ----------------
__device__ float g_M2[D_SZ * C4];            // folded x-projection  [d][col]
__device__ float g_bias2[C4];
__device__ float g_Wp[H_SZ * C4];            // folded recurrent (Wh - We)
__device__ float g_Z[(size_t)B_SZ * T_LEN * C4];   // b-major: [b*T+t][1024]
__device__ float g_hT[2][H_SZ * B_SZ];       // h state [j][b], double buffered
__device__ unsigned g_flagv[NR * FLAG_STR];  // per-CTA progress flags

// ---------------- acquire/release primitives -------------------------------
__device__ __forceinline__ unsigned ld_acq(const void* p) {
    unsigned v;
    asm volatile("ld.acquire.gpu.b32 %0, [%1];" : "=r"(v) : "l"(p) : "memory");
    return v;
}
__device__ __forceinline__ void st_rel(void* p, unsigned v) {
    asm volatile("st.release.gpu.b32 [%0], %1;" :: "l"(p), "r"(v) : "memory");
}

// ---------------- tf32 mma helpers ----------------------------------------
__device__ __forceinline__ unsigned f2tf32(float x) {
    unsigned r;
    asm("cvt.rna.tf32.f32 %0, %1;" : "=r"(r) : "f"(x));
    return r;
}
__device__ __forceinline__ void mma_tf32(float* c, const unsigned* a,
                                         unsigned b0, unsigned b1) {
    asm volatile(
        "mma.sync.aligned.m16n8k8.row.col.f32.tf32.tf32.f32 "
        "{%0,%1,%2,%3}, {%4,%5,%6,%7}, {%8,%9}, {%0,%1,%2,%3};"
        : "+f"(c[0]), "+f"(c[1]), "+f"(c[2]), "+f"(c[3])
        : "r"(a[0]), "r"(a[1]), "r"(a[2]), "r"(a[3]), "r"(b0), "r"(b1));
}

// ---------------- prep kernels --------------------------------------------
__global__ void k_prepM(const float* __restrict__ Win, const float* __restrict__ Wx,
                        const float* __restrict__ We, const float* __restrict__ b) {
    int k = blockIdx.x, d = blockIdx.y, j = threadIdx.x;
    float acc = Wx[(k * D_SZ + d) * H_SZ + j];
    const float* wrow = &Win[d * H_SZ];
#pragma unroll 8
    for (int e = 0; e < H_SZ; e++)
        acc = fmaf(__ldg(&wrow[e]), __ldg(&We[(k * H_SZ + e) * H_SZ + j]), acc);
    g_M2[d * C4 + j * 4 + k] = acc;
    if (d == 0) g_bias2[j * 4 + k] = b[k * H_SZ + j];
}

__global__ void k_prepW(const float* __restrict__ Wh, const float* __restrict__ We) {
    int k = blockIdx.x, h = blockIdx.y, j = threadIdx.x;
    int src = (k * H_SZ + h) * H_SZ + j;
    g_Wp[h * C4 + j * 4 + k] = Wh[src] - We[src];
}

__global__ void k_reset() {
    int i = threadIdx.x;
    if (i < NR * FLAG_STR) g_flagv[i] = 0;
    __threadfence();
}

// ---------------- tiled fp32 GEMM with bias (R4-proven, ~26 TF/s) ----------
template<int BN>
__global__ void __launch_bounds__(256) k_gemm_bias(
    const float* __restrict__ A, const float* __restrict__ Bm,
    const float* __restrict__ bias, float* __restrict__ Cm,
    int N, int K)
{
    const int BM = 128, BK = 16, TM = 8, TN = 4;
    __shared__ float As[BK][BM + 4];
    __shared__ float Bs[BK][BN + 4];

    int tid = threadIdx.x;
    int tx = tid % (BN / TN);
    int ty = tid / (BN / TN);
    int row0 = blockIdx.y * BM;
    int col0 = blockIdx.x * BN;

    float acc[TM][TN];
#pragma unroll
    for (int m = 0; m < TM; m++)
#pragma unroll
        for (int n = 0; n < TN; n++) acc[m][n] = 0.f;

    for (int k0 = 0; k0 < K; k0 += BK) {
#pragma unroll
        for (int i = tid; i < BM * (BK / 4); i += 256) {
            int r  = i >> 2;
            int c4 = i & 3;
            float4 v = *(const float4*)&A[(size_t)(row0 + r) * K + k0 + c4 * 4];
            As[c4 * 4 + 0][r] = v.x;
            As[c4 * 4 + 1][r] = v.y;
            As[c4 * 4 + 2][r] = v.z;
            As[c4 * 4 + 3][r] = v.w;
        }
#pragma unroll
        for (int i = tid; i < BK * (BN / 4); i += 256) {
            int r  = i / (BN / 4);
            int c4 = i % (BN / 4);
            *(float4*)&Bs[r][c4 * 4] =
                *(const float4*)&Bm[(size_t)(k0 + r) * N + col0 + c4 * 4];
        }
        __syncthreads();

#pragma unroll
        for (int k = 0; k < BK; k++) {
            float a[TM], bb[TN];
#pragma unroll
            for (int m = 0; m < TM; m++) a[m] = As[k][ty * TM + m];
#pragma unroll
            for (int n = 0; n < TN; n++) bb[n] = Bs[k][tx * TN + n];
#pragma unroll
            for (int m = 0; m < TM; m++)
#pragma unroll
                for (int n = 0; n < TN; n++)
                    acc[m][n] = fmaf(a[m], bb[n], acc[m][n]);
        }
        __syncthreads();
    }

    float4 bv = *(const float4*)&bias[col0 + tx * TN];
#pragma unroll
    for (int m = 0; m < TM; m++) {
        int r = row0 + ty * TM + m;
        float4 o;
        o.x = acc[m][0] + bv.x;
        o.y = acc[m][1] + bv.y;
        o.z = acc[m][2] + bv.z;
        o.w = acc[m][3] + bv.w;
        *(float4*)&Cm[(size_t)r * N + col0 + tx * TN] = o;
    }
}

// ---------------- phase B: persistent recurrence, flag-synchronized --------
// 64 CTAs, 4 neurons each. Per step: P[64b x 16col] = h[64 x 256] * Wp.
// Sync: all-to-all release flags (no central atomic). flag[c] = 1 + steps done.
__global__ void __launch_bounds__(256, 1) k_recur(
    const float* __restrict__ h_prev, const float* __restrict__ c_prev,
    float* __restrict__ hseq, float* __restrict__ cseq)
{
    extern __shared__ float sm[];
    float* hs = sm;                        // 256*72: h as tf32 [d][b]
    float* pp = sm + H_SZ * HS_STRIDE;     // 2 * 64*20: k-half partials

    const int tid  = threadIdx.x;
    const int cta  = blockIdx.x;
    const int lane = tid & 31;
    const int w    = tid >> 5;
    const int mt   = w & 3;                // m-tile: rows [mt*16, +16)
    const int kh   = w >> 2;               // k-half: d in [kh*128, +128)
    const int b0   = mt * 16;
    const int dbase = kh * 128;
    const int lq = lane >> 2;              // 0..7
    const int lr = lane & 3;               // 0..3

    // Wp B-fragments, 2 n-tiles of 8 cols, register-resident all steps
    unsigned bf00[16], bf01[16], bf10[16], bf11[16];
#pragma unroll
    for (int ks = 0; ks < 16; ks++) {
        int d = dbase + ks * 8;
        int c0 = cta * 16 + lq;
        bf00[ks] = f2tf32(g_Wp[(d + lr)     * C4 + c0]);
        bf01[ks] = f2tf32(g_Wp[(d + 4 + lr) * C4 + c0]);
        bf10[ks] = f2tf32(g_Wp[(d + lr)     * C4 + c0 + 8]);
        bf11[ks] = f2tf32(g_Wp[(d + 4 + lr) * C4 + c0 + 8]);
    }

    // init transposed h state: this CTA's 4 neuron rows
    {
        int jl = tid >> 6, bb = tid & 63;
        g_hT[0][(cta * 4 + jl) * B_SZ + bb] = h_prev[bb * H_SZ + cta * 4 + jl];
    }

    // every thread is a gate thread: (b, local neuron nl)
    const int gb = tid & 63;
    const int nl = tid >> 6;
    const int gj = cta * 4 + nl;
    float creg = c_prev[gb * H_SZ + gj];

    __syncthreads();
    if (tid == 0) { __threadfence(); st_rel(&g_flagv[cta * FLAG_STR], 1u); }

    for (int t = 0; t < T_LEN; t++) {
        const int par = t & 1;

        // wait: all CTAs have published h for step t-1 (flag >= t+1)
        if (tid < NR) {
            const unsigned need = (unsigned)(t + 1);
            while (ld_acq(&g_flagv[tid * FLAG_STR]) < need) { }
            __threadfence();
        }
        __syncthreads();

        // Z prefetch for this gate thread (streams from DRAM under staging)
        const float4 z = __ldg((const float4*)
            &g_Z[(size_t)(gb * T_LEN + t) * C4 + cta * 16 + nl * 4]);

        // stage h [d][b] into smem as tf32 (bypass L1: remote writes)
        const float4* src = (const float4*)&g_hT[par][0];
#pragma unroll
        for (int i = 0; i < 16; i++) {
            int f4  = tid + i * 256;
            float4 v = __ldcg(&src[f4]);
            int row = f4 >> 4;
            int col = (f4 & 15) * 4;
            float* dst = &hs[row * HS_STRIDE + col];
            dst[0] = __uint_as_float(f2tf32(v.x));
            dst[1] = __uint_as_float(f2tf32(v.y));
            dst[2] = __uint_as_float(f2tf32(v.z));
            dst[3] = __uint_as_float(f2tf32(v.w));
        }
        __syncthreads();

        // mma: P[64 x 16] = h[64 x 256(kh half)] * Wp
        float acc0[4] = {0.f, 0.f, 0.f, 0.f};
        float acc1[4] = {0.f, 0.f, 0.f, 0.f};
#pragma unroll
        for (int ks = 0; ks < 16; ks++) {
            int d = dbase + ks * 8;
            const float* p = &hs[(d + lr) * HS_STRIDE + b0 + lq];
            unsigned a[4];
            a[0] = __float_as_uint(p[0]);
            a[1] = __float_as_uint(p[8]);
            a[2] = __float_as_uint(p[4 * HS_STRIDE]);
            a[3] = __float_as_uint(p[4 * HS_STRIDE + 8]);
            mma_tf32(acc0, a, bf00[ks], bf01[ks]);
            mma_tf32(acc1, a, bf10[ks], bf11[ks]);
        }

        // partials: row (b0+lq[,+8]), cols nt*8 + 2*lr
        {
            float* ppk = pp + kh * (B_SZ * 20);
            *(float2*)&ppk[(b0 + lq)     * 20 + lr * 2]     = make_float2(acc0[0], acc0[1]);
            *(float2*)&ppk[(b0 + lq + 8) * 20 + lr * 2]     = make_float2(acc0[2], acc0[3]);
            *(float2*)&ppk[(b0 + lq)     * 20 + 8 + lr * 2] = make_float2(acc1[0], acc1[1]);
            *(float2*)&ppk[(b0 + lq + 8) * 20 + 8 + lr * 2] = make_float2(acc1[2], acc1[3]);
        }
        __syncthreads();

        {
            const float4 q0 = *(const float4*)&pp[gb * 20 + nl * 4];
            const float4 q1 = *(const float4*)&pp[B_SZ * 20 + gb * 20 + nl * 4];
            float p0 = q0.x + q1.x + z.x;
            float p1 = q0.y + q1.y + z.y;
            float p2 = q0.z + q1.z + z.z;
            float p3 = q0.w + q1.w + z.w;

            float f  = 1.f / (1.f + expf(-p0));
            float ig = 1.f / (1.f + expf(-p1));
            float o  = 1.f / (1.f + expf(-p2));
            float g  = tanhf(p3);
            creg = f * creg + ig * g;
            float hn = o * tanhf(creg);

            g_hT[par ^ 1][gj * B_SZ + gb] = hn;
            size_t off = (size_t)(gb * T_LEN + t) * H_SZ + gj;
            hseq[off] = hn;
            cseq[off] = creg;
        }
        __syncthreads();
        if (tid == 0) {
            __threadfence();
            st_rel(&g_flagv[cta * FLAG_STR], (unsigned)(t + 2));
        }
    }
}

// ---------------- launch --------------------------------------------------
extern "C" void kernel_launch(void* const* d_in, const int* in_sizes, int n_in,
                              void* d_out, int out_size) {
    const float* x    = (const float*)d_in[0];
    const float* h0   = (const float*)d_in[1];
    const float* c0   = (const float*)d_in[2];
    const float* Win  = (const float*)d_in[3];
    const float* Wx   = (const float*)d_in[4];
    const float* Wh   = (const float*)d_in[5];
    const float* We   = (const float*)d_in[6];
    const float* bb   = (const float*)d_in[7];
    const float* Wout = (const float*)d_in[8];
    const float* bout = (const float*)d_in[9];

    float* out  = (float*)d_out;
    float* yhat = out;                                   // [B,T,D]
    float* hseq = out + (size_t)B_SZ * T_LEN * D_SZ;     // [B,T,H]
    float* cseq = hseq + (size_t)B_SZ * T_LEN * H_SZ;    // [B,T,H]

    float *pM2, *pbias2, *pZ;
    cudaGetSymbolAddress((void**)&pM2,    g_M2);
    cudaGetSymbolAddress((void**)&pbias2, g_bias2);
    cudaGetSymbolAddress((void**)&pZ,     g_Z);

    // phase 0: fold weights + reset flags
    k_prepM<<<dim3(4, 256), 256>>>(Win, Wx, We, bb);
    k_prepW<<<dim3(4, 256), 256>>>(Wh, We);
    k_reset<<<1, 512>>>();

    // phase A: Z = x * M2 + bias2      (65536 x 1024 x 256)
    k_gemm_bias<64><<<dim3(1024 / 64, 65536 / 128), 256>>>(
        x, pM2, pbias2, pZ, 1024, 256);

    // phase B: serial recurrence (64 CTAs, flag-synchronized, tf32 mma)
    const int smemB = (H_SZ * HS_STRIDE + 2 * B_SZ * 20) * 4;   // 83968 B
    cudaFuncSetAttribute(k_recur, cudaFuncAttributeMaxDynamicSharedMemorySize,
                         smemB);
    k_recur<<<NR, 256, smemB>>>(h0, c0, hseq, cseq);

    // phase C: y = h_seq * W_out + b_out   (65536 x 256 x 256)
    k_gemm_bias<64><<<dim3(256 / 64, 65536 / 128), 256>>>(
        hseq, Wout, bout, yhat, 256, 256);
}

// round 12
// speedup vs baseline: 1.0956x; 1.0956x over previous
#include <cuda_runtime.h>
#include <math.h>

#define T_LEN 1024
#define B_SZ  64
#define H_SZ  256
#define D_SZ  256
#define C4    1024          // 4*H, col = j*4 + k (gates of a neuron contiguous)
#define NRC   128           // recurrent CTAs, 2 neurons (8 gate cols) each
#define HS_STRIDE 72        // padded word stride for hs[d][b]
#define FLAG_STR 8          // 32B padding between flags

// ---------------- scratch (static device allocations only) ----------------
__device__ float g_M2[D_SZ * C4];            // folded x-projection  [d][col]
__device__ float g_bias2[C4];
__device__ float g_Wp[H_SZ * C4];            // folded recurrent (Wh - We)
__device__ float g_Z[(size_t)B_SZ * T_LEN * C4];   // b-major: [b*T+t][1024]
__device__ float g_hT[2][H_SZ * B_SZ];       // h state [j][b], double buffered
__device__ unsigned g_flagv[NRC * FLAG_STR]; // per-CTA progress flags

// ---------------- acquire/release primitives -------------------------------
__device__ __forceinline__ unsigned ld_acq(const void* p) {
    unsigned v;
    asm volatile("ld.acquire.gpu.b32 %0, [%1];" : "=r"(v) : "l"(p) : "memory");
    return v;
}
__device__ __forceinline__ void st_rel(void* p, unsigned v) {
    asm volatile("st.release.gpu.b32 [%0], %1;" :: "l"(p), "r"(v) : "memory");
}

// ---------------- tf32 mma helpers ----------------------------------------
__device__ __forceinline__ unsigned f2tf32(float x) {
    unsigned r;
    asm("cvt.rna.tf32.f32 %0, %1;" : "=r"(r) : "f"(x));
    return r;
}
__device__ __forceinline__ void mma_tf32(float* c, const unsigned* a,
                                         unsigned b0, unsigned b1) {
    asm volatile(
        "mma.sync.aligned.m16n8k8.row.col.f32.tf32.tf32.f32 "
        "{%0,%1,%2,%3}, {%4,%5,%6,%7}, {%8,%9}, {%0,%1,%2,%3};"
        : "+f"(c[0]), "+f"(c[1]), "+f"(c[2]), "+f"(c[3])
        : "r"(a[0]), "r"(a[1]), "r"(a[2]), "r"(a[3]), "r"(b0), "r"(b1));
}

// ---------------- prep kernels --------------------------------------------
__global__ void k_prepM(const float* __restrict__ Win, const float* __restrict__ Wx,
                        const float* __restrict__ We, const float* __restrict__ b) {
    int k = blockIdx.x, d = blockIdx.y, j = threadIdx.x;
    float acc = Wx[(k * D_SZ + d) * H_SZ + j];
    const float* wrow = &Win[d * H_SZ];
#pragma unroll 8
    for (int e = 0; e < H_SZ; e++)
        acc = fmaf(__ldg(&wrow[e]), __ldg(&We[(k * H_SZ + e) * H_SZ + j]), acc);
    g_M2[d * C4 + j * 4 + k] = acc;
    if (d == 0) g_bias2[j * 4 + k] = b[k * H_SZ + j];
}

__global__ void k_prepW(const float* __restrict__ Wh, const float* __restrict__ We) {
    int k = blockIdx.x, h = blockIdx.y, j = threadIdx.x;
    int src = (k * H_SZ + h) * H_SZ + j;
    g_Wp[h * C4 + j * 4 + k] = Wh[src] - We[src];
}

__global__ void k_reset() {
    g_flagv[threadIdx.x] = 0;
    __threadfence();
}

// ---------------- tiled fp32 GEMM with bias (proven ~60% FFMA) -------------
template<int BN>
__global__ void __launch_bounds__(256) k_gemm_bias(
    const float* __restrict__ A, const float* __restrict__ Bm,
    const float* __restrict__ bias, float* __restrict__ Cm,
    int N, int K)
{
    const int BM = 128, BK = 16, TM = 8, TN = 4;
    __shared__ float As[BK][BM + 4];
    __shared__ float Bs[BK][BN + 4];

    int tid = threadIdx.x;
    int tx = tid % (BN / TN);
    int ty = tid / (BN / TN);
    int row0 = blockIdx.y * BM;
    int col0 = blockIdx.x * BN;

    float acc[TM][TN];
#pragma unroll
    for (int m = 0; m < TM; m++)
#pragma unroll
        for (int n = 0; n < TN; n++) acc[m][n] = 0.f;

    for (int k0 = 0; k0 < K; k0 += BK) {
#pragma unroll
        for (int i = tid; i < BM * (BK / 4); i += 256) {
            int r  = i >> 2;
            int c4 = i & 3;
            float4 v = *(const float4*)&A[(size_t)(row0 + r) * K + k0 + c4 * 4];
            As[c4 * 4 + 0][r] = v.x;
            As[c4 * 4 + 1][r] = v.y;
            As[c4 * 4 + 2][r] = v.z;
            As[c4 * 4 + 3][r] = v.w;
        }
#pragma unroll
        for (int i = tid; i < BK * (BN / 4); i += 256) {
            int r  = i / (BN / 4);
            int c4 = i % (BN / 4);
            *(float4*)&Bs[r][c4 * 4] =
                *(const float4*)&Bm[(size_t)(k0 + r) * N + col0 + c4 * 4];
        }
        __syncthreads();

#pragma unroll
        for (int k = 0; k < BK; k++) {
            float a[TM], bb[TN];
#pragma unroll
            for (int m = 0; m < TM; m++) a[m] = As[k][ty * TM + m];
#pragma unroll
            for (int n = 0; n < TN; n++) bb[n] = Bs[k][tx * TN + n];
#pragma unroll
            for (int m = 0; m < TM; m++)
#pragma unroll
                for (int n = 0; n < TN; n++)
                    acc[m][n] = fmaf(a[m], bb[n], acc[m][n]);
        }
        __syncthreads();
    }

    float4 bv = *(const float4*)&bias[col0 + tx * TN];
#pragma unroll
    for (int m = 0; m < TM; m++) {
        int r = row0 + ty * TM + m;
        float4 o;
        o.x = acc[m][0] + bv.x;
        o.y = acc[m][1] + bv.y;
        o.z = acc[m][2] + bv.z;
        o.w = acc[m][3] + bv.w;
        *(float4*)&Cm[(size_t)r * N + col0 + tx * TN] = o;
    }
}

// ---------------- phase B: persistent recurrence, dataflow flags -----------
// 128 CTAs, 2 neurons (8 gate cols) each. Per step:
//   P[64b x 8col] = h[64 x 256] * Wp, tf32 mma, Wp fragments in registers.
// Sync: per-producer release flags; warp w polls its 16 producers, then
// stages their contiguous 8KB of h. No central atomic, no global barrier.
// Critical path per step: 1 publish->observe hop + slice load + mma + gates.
__global__ void __launch_bounds__(256, 1) k_recur(
    const float* __restrict__ h_prev, const float* __restrict__ c_prev,
    float* __restrict__ hseq, float* __restrict__ cseq)
{
    extern __shared__ float sm[];
    float* hs = sm;                        // 256*72: h as tf32 [d][b]
    float* pp = sm + H_SZ * HS_STRIDE;     // 2 * 64*12: k-half partials

    const int tid  = threadIdx.x;
    const int cta  = blockIdx.x;
    const int lane = tid & 31;
    const int w    = tid >> 5;
    const int mt   = w & 3;                // m-tile: rows [mt*16, +16)
    const int kh   = w >> 2;               // k-half: d in [kh*128, +128)
    const int b0   = mt * 16;
    const int dbase = kh * 128;
    const int lq = lane >> 2;              // 0..7
    const int lr = lane & 3;               // 0..3

    // Wp B-fragments (8 cols), register-resident for all steps
    unsigned bf0[16], bf1[16];
#pragma unroll
    for (int ks = 0; ks < 16; ks++) {
        int d = dbase + ks * 8;
        int c0 = cta * 8 + lq;
        bf0[ks] = f2tf32(g_Wp[(d + lr)     * C4 + c0]);
        bf1[ks] = f2tf32(g_Wp[(d + 4 + lr) * C4 + c0]);
    }

    // init transposed h state: this CTA's 2 neuron rows
    if (tid < 128) {
        int jl = tid >> 6, bb = tid & 63;
        g_hT[0][(cta * 2 + jl) * B_SZ + bb] = h_prev[bb * H_SZ + cta * 2 + jl];
    }

    // gate threads (tid < 128): own (b, local neuron)
    const int gb  = tid >> 1;
    const int gjl = tid & 1;
    const int gj  = cta * 2 + gjl;
    float creg = 0.f;
    if (tid < 128) creg = c_prev[gb * H_SZ + gj];

    __syncthreads();
    if (tid == 0) { __threadfence(); st_rel(&g_flagv[cta * FLAG_STR], 1u); }

    // each lane polls one producer flag (2 lanes per flag)
    const unsigned* myflag = &g_flagv[(w * 16 + (lane & 15)) * FLAG_STR];

    for (int t = 0; t < T_LEN; t++) {
        const int par = t & 1;

        // Z prefetch (independent of flags; overlaps the wait)
        float4 z = make_float4(0.f, 0.f, 0.f, 0.f);
        if (tid < 128)
            z = __ldg((const float4*)
                &g_Z[(size_t)(gb * T_LEN + t) * C4 + cta * 8 + gjl * 4]);

        // dataflow wait: this warp's 16 producers published h for step t
        {
            const unsigned need = (unsigned)(t + 1);
            while (!__all_sync(0xffffffffu, ld_acq(myflag) >= need)) { }
        }

        // stage this warp's 16 slices (contiguous 8KB region), cvt to tf32
        const float4* src = (const float4*)&g_hT[par][0];
#pragma unroll
        for (int i = 0; i < 16; i++) {
            int F = w * 512 + i * 32 + lane;       // global float4 index
            float4 v = __ldcg(&src[F]);
            int row = F >> 4;
            int col = (F & 15) * 4;
            float* dst = &hs[row * HS_STRIDE + col];
            dst[0] = __uint_as_float(f2tf32(v.x));
            dst[1] = __uint_as_float(f2tf32(v.y));
            dst[2] = __uint_as_float(f2tf32(v.z));
            dst[3] = __uint_as_float(f2tf32(v.w));
        }
        __syncthreads();

        // mma over this warp's k-half, two interleaved acc chains
        float acc0[4] = {0.f, 0.f, 0.f, 0.f};
        float acc1[4] = {0.f, 0.f, 0.f, 0.f};
#pragma unroll
        for (int ks = 0; ks < 16; ks += 2) {
            unsigned a[4];
            {
                int d = dbase + ks * 8;
                const float* p = &hs[(d + lr) * HS_STRIDE + b0 + lq];
                a[0] = __float_as_uint(p[0]);
                a[1] = __float_as_uint(p[8]);
                a[2] = __float_as_uint(p[4 * HS_STRIDE]);
                a[3] = __float_as_uint(p[4 * HS_STRIDE + 8]);
                mma_tf32(acc0, a, bf0[ks], bf1[ks]);
            }
            {
                int d = dbase + (ks + 1) * 8;
                const float* p = &hs[(d + lr) * HS_STRIDE + b0 + lq];
                a[0] = __float_as_uint(p[0]);
                a[1] = __float_as_uint(p[8]);
                a[2] = __float_as_uint(p[4 * HS_STRIDE]);
                a[3] = __float_as_uint(p[4 * HS_STRIDE + 8]);
                mma_tf32(acc1, a, bf0[ks + 1], bf1[ks + 1]);
            }
        }
        acc0[0] += acc1[0]; acc0[1] += acc1[1];
        acc0[2] += acc1[2]; acc0[3] += acc1[3];

        // partials: row (b0+lq[,+8]), cols 2*lr, pitch 12
        {
            float* ppk = pp + kh * (B_SZ * 12);
            *(float2*)&ppk[(b0 + lq)     * 12 + lr * 2] = make_float2(acc0[0], acc0[1]);
            *(float2*)&ppk[(b0 + lq + 8) * 12 + lr * 2] = make_float2(acc0[2], acc0[3]);
        }
        __syncthreads();

        float hn = 0.f;
        if (tid < 128) {
            const float4 q0 = *(const float4*)&pp[gb * 12 + gjl * 4];
            const float4 q1 = *(const float4*)&pp[B_SZ * 12 + gb * 12 + gjl * 4];
            float p0 = q0.x + q1.x + z.x;
            float p1 = q0.y + q1.y + z.y;
            float p2 = q0.z + q1.z + z.z;
            float p3 = q0.w + q1.w + z.w;

            float f  = 1.f / (1.f + expf(-p0));
            float ig = 1.f / (1.f + expf(-p1));
            float o  = 1.f / (1.f + expf(-p2));
            float g  = tanhf(p3);
            creg = f * creg + ig * g;
            hn = o * tanhf(creg);

            // critical-path publish: only the 512B hT slice
            g_hT[par ^ 1][gj * B_SZ + gb] = hn;
        }
        __syncthreads();
        if (tid == 0) {
            __threadfence();
            st_rel(&g_flagv[cta * FLAG_STR], (unsigned)(t + 2));
        }
        // off-critical-path outputs (nothing reads these until phase C)
        if (tid < 128) {
            size_t off = (size_t)(gb * T_LEN + t) * H_SZ + gj;
            hseq[off] = hn;
            cseq[off] = creg;
        }
    }
}

// ---------------- launch --------------------------------------------------
extern "C" void kernel_launch(void* const* d_in, const int* in_sizes, int n_in,
                              void* d_out, int out_size) {
    const float* x    = (const float*)d_in[0];
    const float* h0   = (const float*)d_in[1];
    const float* c0   = (const float*)d_in[2];
    const float* Win  = (const float*)d_in[3];
    const float* Wx   = (const float*)d_in[4];
    const float* Wh   = (const float*)d_in[5];
    const float* We   = (const float*)d_in[6];
    const float* bb   = (const float*)d_in[7];
    const float* Wout = (const float*)d_in[8];
    const float* bout = (const float*)d_in[9];

    float* out  = (float*)d_out;
    float* yhat = out;                                   // [B,T,D]
    float* hseq = out + (size_t)B_SZ * T_LEN * D_SZ;     // [B,T,H]
    float* cseq = hseq + (size_t)B_SZ * T_LEN * H_SZ;    // [B,T,H]

    float *pM2, *pbias2, *pZ;
    cudaGetSymbolAddress((void**)&pM2,    g_M2);
    cudaGetSymbolAddress((void**)&pbias2, g_bias2);
    cudaGetSymbolAddress((void**)&pZ,     g_Z);

    // phase 0: fold weights + reset flags
    k_prepM<<<dim3(4, 256), 256>>>(Win, Wx, We, bb);
    k_prepW<<<dim3(4, 256), 256>>>(Wh, We);
    k_reset<<<1, NRC * FLAG_STR>>>();

    // phase A: Z = x * M2 + bias2      (65536 x 1024 x 256)
    k_gemm_bias<64><<<dim3(1024 / 64, 65536 / 128), 256>>>(
        x, pM2, pbias2, pZ, 1024, 256);

    // phase B: serial recurrence (128 CTAs, dataflow flags, tf32 mma)
    const int smemB = (H_SZ * HS_STRIDE + 2 * B_SZ * 12) * 4;   // 79872 B
    cudaFuncSetAttribute(k_recur, cudaFuncAttributeMaxDynamicSharedMemorySize,
                         smemB);
    k_recur<<<NRC, 256, smemB>>>(h0, c0, hseq, cseq);

    // phase C: y = h_seq * W_out + b_out   (65536 x 256 x 256)
    k_gemm_bias<64><<<dim3(256 / 64, 65536 / 128), 256>>>(
        hseq, Wout, bout, yhat, 256, 256);
}